// round 1
// baseline (speedup 1.0000x reference)
#include <cuda_runtime.h>
#include <math.h>

#define EPSF 1e-6f
#define BLK 128

struct V3 { float x, y, z; };

__device__ __forceinline__ V3 operator+(V3 a, V3 b){ return {a.x+b.x, a.y+b.y, a.z+b.z}; }
__device__ __forceinline__ V3 operator-(V3 a, V3 b){ return {a.x-b.x, a.y-b.y, a.z-b.z}; }
__device__ __forceinline__ V3 operator*(V3 a, float s){ return {a.x*s, a.y*s, a.z*s}; }
__device__ __forceinline__ float dot3(V3 a, V3 b){ return a.x*b.x + a.y*b.y + a.z*b.z; }
__device__ __forceinline__ V3 cross3(V3 a, V3 b){
    return { a.y*b.z - a.z*b.y, a.z*b.x - a.x*b.z, a.x*b.y - a.y*b.x };
}
__device__ __forceinline__ float nrm3(V3 a){ return sqrtf(dot3(a,a)); }
__device__ __forceinline__ V3 unitv(V3 a){ float inv = 1.0f/(nrm3(a)+EPSF); return a*inv; }
__device__ __forceinline__ float clampd(float x){ return fminf(fmaxf(x, -1.0f+EPSF), 1.0f-EPSF); }

struct M3 { float a[9]; };

__device__ __forceinline__ V3 mv(const M3& R, V3 v){
    return { R.a[0]*v.x + R.a[1]*v.y + R.a[2]*v.z,
             R.a[3]*v.x + R.a[4]*v.y + R.a[5]*v.z,
             R.a[6]*v.x + R.a[7]*v.y + R.a[8]*v.z };
}
__device__ __forceinline__ V3 mtv(const M3& R, V3 v){
    return { R.a[0]*v.x + R.a[3]*v.y + R.a[6]*v.z,
             R.a[1]*v.x + R.a[4]*v.y + R.a[7]*v.z,
             R.a[2]*v.x + R.a[5]*v.y + R.a[8]*v.z };
}

// Rodrigues matrix (axis re-normalized with +EPS, matching reference)
__device__ __forceinline__ M3 rotmat(V3 axis, float c, float s){
    float inv = 1.0f/(nrm3(axis)+EPSF);
    float x = axis.x*inv, y = axis.y*inv, z = axis.z*inv;
    float C = 1.0f - c;
    M3 R;
    R.a[0] = c + x*x*C;   R.a[1] = x*y*C - z*s; R.a[2] = x*z*C + y*s;
    R.a[3] = y*x*C + z*s; R.a[4] = c + y*y*C;   R.a[5] = y*z*C - x*s;
    R.a[6] = z*x*C - y*s; R.a[7] = z*y*C + x*s; R.a[8] = c + z*z*C;
    return R;
}

// getrot: builds R(+dif) once; R(-dif) == R(+dif)^T exactly in fp32.
__device__ __forceinline__ M3 getrot(float angle, float flexRatio, V3 axis, V3 sv, V3 ev){
    const float ANGLEP = 0.34906585039886590f;  // pi/9
    const float TH120  = 2.09439506666666650f;  // 3.1415926/180*120
    angle = (angle > TH120) ? (3.1415926f - angle) : angle;
    float dif = fmaxf(angle - ANGLEP, 0.0f) * flexRatio;
    float s, c;
    sincosf(dif, &s, &c);
    M3 R = rotmat(axis, c, s);
    // unit() scaling is identical for both candidates -> compare raw dots
    float d0 = dot3(mv (R, sv), ev);
    float d1 = dot3(mtv(R, sv), ev);
    if (!(fabsf(d0) > fabsf(d1))) {  // reference picks r1 on tie
        float t;
        t = R.a[1]; R.a[1] = R.a[3]; R.a[3] = t;
        t = R.a[2]; R.a[2] = R.a[6]; R.a[6] = t;
        t = R.a[5]; R.a[5] = R.a[7]; R.a[7] = t;
    }
    return R;
}

// Smallest eigenvector of symmetric 3x3 (analytic + one Rayleigh refinement).
// Sign is irrelevant to the downstream plane projection.
__device__ __forceinline__ V3 smallest_evec(float a00, float a01, float a02,
                                            float a11, float a12, float a22){
    float m   = (a00 + a11 + a22) * (1.0f/3.0f);
    float b00 = a00 - m, b11 = a11 - m, b22 = a22 - m;
    float p1  = a01*a01 + a02*a02 + a12*a12;
    float p2  = b00*b00 + b11*b11 + b22*b22 + 2.0f*p1;
    float p   = sqrtf(fmaxf(p2*(1.0f/6.0f), 1e-30f));
    float invp = 1.0f/p;
    float det = b00*(b11*b22 - a12*a12)
              - a01*(a01*b22 - a12*a02)
              + a02*(a01*a12 - b11*a02);
    float r = det * 0.5f * invp*invp*invp;
    r = fminf(fmaxf(r, -1.0f), 1.0f);
    float phi = acosf(r) * (1.0f/3.0f);
    float lam = m + 2.0f*p*cosf(phi + 2.0943951023931953f); // smallest eigenvalue

    V3 r0 = { a00 - lam, a01, a02 };
    V3 r1 = { a01, a11 - lam, a12 };
    V3 r2 = { a02, a12, a22 - lam };
    V3 c0 = cross3(r0, r1), c1 = cross3(r0, r2), c2 = cross3(r1, r2);
    float l0 = dot3(c0,c0), l1 = dot3(c1,c1), l2 = dot3(c2,c2);
    V3 best = c0; float lb = l0;
    if (l1 > lb) { best = c1; lb = l1; }
    if (l2 > lb) { best = c2; lb = l2; }
    V3 v = best * rsqrtf(fmaxf(lb, 1e-30f));

    // one Rayleigh-quotient refinement of lambda, then recompute eigenvector
    float Av0 = a00*v.x + a01*v.y + a02*v.z;
    float Av1 = a01*v.x + a11*v.y + a12*v.z;
    float Av2 = a02*v.x + a12*v.y + a22*v.z;
    float lam2 = v.x*Av0 + v.y*Av1 + v.z*Av2;
    r0 = { a00 - lam2, a01, a02 };
    r1 = { a01, a11 - lam2, a12 };
    r2 = { a02, a12, a22 - lam2 };
    c0 = cross3(r0, r1); c1 = cross3(r0, r2); c2 = cross3(r1, r2);
    l0 = dot3(c0,c0); l1 = dot3(c1,c1); l2 = dot3(c2,c2);
    best = c0; lb = l0;
    if (l1 > lb) { best = c1; lb = l1; }
    if (l2 > lb) { best = c2; lb = l2; }
    return best * rsqrtf(fmaxf(lb, 1e-30f));
}

// planarize one finger (4 joints, modified in place)
__device__ __forceinline__ void plan4(V3& p0, V3& p1, V3& p2, V3& p3){
    V3 cm = (p0 + p1 + p2 + p3) * 0.25f;
    V3 d0 = p0 - cm, d1 = p1 - cm, d2 = p2 - cm, d3 = p3 - cm;
    float a00 = d0.x*d0.x + d1.x*d1.x + d2.x*d2.x + d3.x*d3.x;
    float a01 = d0.x*d0.y + d1.x*d1.y + d2.x*d2.y + d3.x*d3.y;
    float a02 = d0.x*d0.z + d1.x*d1.z + d2.x*d2.z + d3.x*d3.z;
    float a11 = d0.y*d0.y + d1.y*d1.y + d2.y*d2.y + d3.y*d3.y;
    float a12 = d0.y*d0.z + d1.y*d1.z + d2.y*d2.z + d3.y*d3.z;
    float a22 = d0.z*d0.z + d1.z*d1.z + d2.z*d2.z + d3.z*d3.z;
    V3 n = smallest_evec(a00, a01, a02, a11, a12, a22);
    float vd = -dot3(n, cm);
    float t;
    t = dot3(p0, n) + vd; p0 = p0 - n*t;
    t = dot3(p1, n) + vd; p1 = p1 - n*t;
    t = dot3(p2, n) + vd; p2 = p2 - n*t;
    t = dot3(p3, n) + vd; p3 = p3 - n*t;
}

// abduction for one finger; c0..c2 = children {PIP, DIP, TIP} (refs), mcp/pip by value
__device__ __forceinline__ void abduct(V3 w, V3 pa, V3 pb, float rectAng,
                                       V3 mcp, V3 pip, V3& c0, V3& c1, V3& c2){
    V3 palm = unitv(cross3(pa, pb));
    float vd   = -dot3(mcp, palm);
    float dist = dot3(pip, palm) + vd;
    V3 projpip = pip - palm*dist;
    float dis  = nrm3(mcp - pip);
    float flex = nrm3(projpip - mcp) / (dis + EPSF);
    flex = (flex < 0.3f) ? 0.0f : flex;
    V3 wristmcp = unitv(mcp - w);
    V3 mcpproj  = unitv(projpip - mcp);
    V3 mcppip   = unitv(pip - mcp);
    float cv = clampd(dot3(wristmcp, mcppip));
    bool overflex = cv < 0.00079632671073326f;   // == acos(cv) > 1.57
    float rs, rc;
    sincosf(rectAng, &rs, &rc);
    M3 Rr = rotmat(palm, rc, rs);
    V3 rect = mv(Rr, wristmcp);
    float ang = acosf(clampd(dot3(rect, mcpproj)));
    if (overflex) ang = 0.0f;
    M3 R = getrot(ang, flex, palm, mcpproj, wristmcp);
    c0 = mv(R, c0 - mcp) + mcp;
    c1 = mv(R, c1 - mcp) + mcp;
    c2 = mv(R, c2 - mcp) + mcp;
}

// plane rotation for one finger; rotates DIP & TIP about PIP
__device__ __forceinline__ void planerot(V3 w, V3 pa, V3 pb,
                                         V3 mcp, V3 pip, V3 dip, V3& dref, V3& tref){
    V3 mcppip = unitv(pip - mcp);
    V3 pipdip = unitv(dip - pip);
    bool maskline = fabsf(dot3(mcppip, pipdip)) > 0.95f;
    V3 cdir = unitv(cross3(mcppip, pipdip));
    V3 palm = unitv(cross3(pa, pb));
    V3 stdv = unitv(cross3(unitv(mcp - w), palm));
    float ang = acosf(clampd(dot3(cdir, stdv)));
    if (maskline) ang = 0.0f;
    M3 R = getrot(ang, 1.0f, mcppip, cdir, stdv);
    dref = mv(R, dref - pip) + pip;
    tref = mv(R, tref - pip) + pip;
}

__global__ void handpose_kernel(const float* __restrict__ in,
                                float* __restrict__ out, int N){
    __shared__ float s[BLK * 63];
    int base = blockIdx.x * BLK;
    int nE = N - base; if (nE > BLK) nE = BLK;
    int nF = nE * 63;
    const float* gin = in + (long long)base * 63;

    for (int k = threadIdx.x; k < nF; k += BLK) s[k] = gin[k];
    __syncthreads();

    if ((int)threadIdx.x < nE) {
        float* sp = s + threadIdx.x * 63;
        V3 J[21];
        #pragma unroll
        for (int j = 0; j < 21; j++) J[j] = { sp[3*j], sp[3*j+1], sp[3*j+2] };

        // ---- planarize #1 ----
        plan4(J[1],  J[2],  J[3],  J[17]);
        plan4(J[4],  J[5],  J[6],  J[18]);
        plan4(J[10], J[11], J[12], J[19]);
        plan4(J[7],  J[8],  J[9],  J[20]);
        plan4(J[13], J[14], J[15], J[16]);

        // ---- abduction ----  (geometry reads only wrist/MCPs/own PIP: in-place == snapshot)
        {
            V3 w = J[0];
            abduct(w, J[1]-w,  J[4]-w,  0.189f,  J[1],  J[2],  J[2],  J[3],  J[17]);
            abduct(w, J[4]-w,  J[10]-w, 0.1331f, J[4],  J[5],  J[5],  J[6],  J[18]);
            abduct(w, J[10]-w, J[7]-w, -0.1491f, J[10], J[11], J[11], J[12], J[19]);
            abduct(w, J[7]-w,  J[1]-w,  0.0347f, J[7],  J[8],  J[8],  J[9],  J[20]);
            abduct(w, J[13]-w, J[1]-w,  0.0f,    J[13], J[14], J[14], J[15], J[16]);
        }

        // ---- plane rotation (fingers 0..3) ----
        {
            V3 w = J[0];
            planerot(w, J[1]-w,  J[4]-w,  J[1],  J[2],  J[3],  J[3],  J[17]);
            planerot(w, J[4]-w,  J[10]-w, J[4],  J[5],  J[6],  J[6],  J[18]);
            planerot(w, J[10]-w, J[7]-w,  J[10], J[11], J[12], J[12], J[19]);
            planerot(w, J[7]-w,  J[1]-w,  J[7],  J[8],  J[9],  J[9],  J[20]);
        }

        // ---- planarize #2 ----
        plan4(J[1],  J[2],  J[3],  J[17]);
        plan4(J[4],  J[5],  J[6],  J[18]);
        plan4(J[10], J[11], J[12], J[19]);
        plan4(J[7],  J[8],  J[9],  J[20]);
        plan4(J[13], J[14], J[15], J[16]);

        #pragma unroll
        for (int j = 0; j < 21; j++) {
            sp[3*j]   = J[j].x;
            sp[3*j+1] = J[j].y;
            sp[3*j+2] = J[j].z;
        }
    }
    __syncthreads();

    float* gout = out + (long long)base * 63;
    for (int k = threadIdx.x; k < nF; k += BLK) gout[k] = s[k];
}

extern "C" void kernel_launch(void* const* d_in, const int* in_sizes, int n_in,
                              void* d_out, int out_size){
    const float* in = (const float*)d_in[0];
    float* out = (float*)d_out;
    int N = in_sizes[0] / 63;
    int grid = (N + BLK - 1) / BLK;
    handpose_kernel<<<grid, BLK>>>(in, out, N);
}

// round 2
// speedup vs baseline: 1.1992x; 1.1992x over previous
#include <cuda_runtime.h>
#include <math.h>

#define EPSF 1e-6f
#define BLK 128

struct V3 { float x, y, z; };

__device__ __forceinline__ V3 operator+(V3 a, V3 b){ return {a.x+b.x, a.y+b.y, a.z+b.z}; }
__device__ __forceinline__ V3 operator-(V3 a, V3 b){ return {a.x-b.x, a.y-b.y, a.z-b.z}; }
__device__ __forceinline__ V3 operator*(V3 a, float s){ return {a.x*s, a.y*s, a.z*s}; }
__device__ __forceinline__ float dot3(V3 a, V3 b){ return a.x*b.x + a.y*b.y + a.z*b.z; }
__device__ __forceinline__ V3 cross3(V3 a, V3 b){
    return { a.y*b.z - a.z*b.y, a.z*b.x - a.x*b.z, a.x*b.y - a.y*b.x };
}
__device__ __forceinline__ float nrm3(V3 a){ return sqrtf(dot3(a,a)); }
__device__ __forceinline__ V3 unitv(V3 a){ float inv = 1.0f/(nrm3(a)+EPSF); return a*inv; }
__device__ __forceinline__ float clampd(float x){ return fminf(fmaxf(x, -1.0f+EPSF), 1.0f-EPSF); }

struct M3 { float a[9]; };

__device__ __forceinline__ V3 mv(const M3& R, V3 v){
    return { R.a[0]*v.x + R.a[1]*v.y + R.a[2]*v.z,
             R.a[3]*v.x + R.a[4]*v.y + R.a[5]*v.z,
             R.a[6]*v.x + R.a[7]*v.y + R.a[8]*v.z };
}
__device__ __forceinline__ V3 mtv(const M3& R, V3 v){
    return { R.a[0]*v.x + R.a[3]*v.y + R.a[6]*v.z,
             R.a[1]*v.x + R.a[4]*v.y + R.a[7]*v.z,
             R.a[2]*v.x + R.a[5]*v.y + R.a[8]*v.z };
}

// smem joint accessors (per-thread stride 63 floats; odd stride -> conflict-free)
__device__ __forceinline__ V3 ld3(const float* sp, int j){
    return { sp[3*j], sp[3*j+1], sp[3*j+2] };
}
__device__ __forceinline__ void st3(float* sp, int j, V3 v){
    sp[3*j] = v.x; sp[3*j+1] = v.y; sp[3*j+2] = v.z;
}

// Rodrigues matrix (axis re-normalized with +EPS, matching reference)
__device__ __forceinline__ M3 rotmat(V3 axis, float c, float s){
    float inv = 1.0f/(nrm3(axis)+EPSF);
    float x = axis.x*inv, y = axis.y*inv, z = axis.z*inv;
    float C = 1.0f - c;
    M3 R;
    R.a[0] = c + x*x*C;   R.a[1] = x*y*C - z*s; R.a[2] = x*z*C + y*s;
    R.a[3] = y*x*C + z*s; R.a[4] = c + y*y*C;   R.a[5] = y*z*C - x*s;
    R.a[6] = z*x*C - y*s; R.a[7] = z*y*C + x*s; R.a[8] = c + z*z*C;
    return R;
}

// getrot: builds R(+dif) once; R(-dif) == R(+dif)^T (bitwise identical entries).
__device__ __forceinline__ M3 getrot(float angle, float flexRatio, V3 axis, V3 sv, V3 ev){
    const float ANGLEP = 0.34906585039886590f;  // pi/9
    const float TH120  = 2.09439506666666650f;  // 3.1415926/180*120
    angle = (angle > TH120) ? (3.1415926f - angle) : angle;
    float dif = fmaxf(angle - ANGLEP, 0.0f) * flexRatio;
    float s, c;
    sincosf(dif, &s, &c);
    M3 R = rotmat(axis, c, s);
    float d0 = dot3(mv (R, sv), ev);
    float d1 = dot3(mtv(R, sv), ev);
    if (!(fabsf(d0) > fabsf(d1))) {  // reference picks r1 on tie
        float t;
        t = R.a[1]; R.a[1] = R.a[3]; R.a[3] = t;
        t = R.a[2]; R.a[2] = R.a[6]; R.a[6] = t;
        t = R.a[5]; R.a[5] = R.a[7]; R.a[7] = t;
    }
    return R;
}

// Smallest eigenvector of symmetric 3x3 (analytic + two Rayleigh refinements).
__device__ __forceinline__ V3 smallest_evec(float a00, float a01, float a02,
                                            float a11, float a12, float a22){
    float m   = (a00 + a11 + a22) * (1.0f/3.0f);
    float b00 = a00 - m, b11 = a11 - m, b22 = a22 - m;
    float p1  = a01*a01 + a02*a02 + a12*a12;
    float p2  = b00*b00 + b11*b11 + b22*b22 + 2.0f*p1;
    float p   = sqrtf(fmaxf(p2*(1.0f/6.0f), 1e-30f));
    float invp = 1.0f/p;
    float det = b00*(b11*b22 - a12*a12)
              - a01*(a01*b22 - a12*a02)
              + a02*(a01*a12 - b11*a02);
    float r = det * 0.5f * invp*invp*invp;
    r = fminf(fmaxf(r, -1.0f), 1.0f);
    float phi = acosf(r) * (1.0f/3.0f);
    float lam = m + 2.0f*p*cosf(phi + 2.0943951023931953f); // smallest eigenvalue

    V3 v;
    #pragma unroll
    for (int it = 0; it < 3; it++) {
        V3 r0 = { a00 - lam, a01, a02 };
        V3 r1 = { a01, a11 - lam, a12 };
        V3 r2 = { a02, a12, a22 - lam };
        V3 c0 = cross3(r0, r1), c1 = cross3(r0, r2), c2 = cross3(r1, r2);
        float l0 = dot3(c0,c0), l1 = dot3(c1,c1), l2 = dot3(c2,c2);
        V3 best = c0; float lb = l0;
        if (l1 > lb) { best = c1; lb = l1; }
        if (l2 > lb) { best = c2; lb = l2; }
        v = best * rsqrtf(fmaxf(lb, 1e-30f));
        if (it < 2) {
            // Rayleigh-quotient refinement of lambda
            float Av0 = a00*v.x + a01*v.y + a02*v.z;
            float Av1 = a01*v.x + a11*v.y + a12*v.z;
            float Av2 = a02*v.x + a12*v.y + a22*v.z;
            lam = v.x*Av0 + v.y*Av1 + v.z*Av2;
        }
    }
    return v;
}

// planarize one finger (4 joints in smem, modified in place)
__device__ __forceinline__ void plan4(float* sp, int i0, int i1, int i2, int i3){
    V3 p0 = ld3(sp,i0), p1 = ld3(sp,i1), p2 = ld3(sp,i2), p3 = ld3(sp,i3);
    V3 cm = (p0 + p1 + p2 + p3) * 0.25f;
    V3 d0 = p0 - cm, d1 = p1 - cm, d2 = p2 - cm, d3 = p3 - cm;
    float a00 = d0.x*d0.x + d1.x*d1.x + d2.x*d2.x + d3.x*d3.x;
    float a01 = d0.x*d0.y + d1.x*d1.y + d2.x*d2.y + d3.x*d3.y;
    float a02 = d0.x*d0.z + d1.x*d1.z + d2.x*d2.z + d3.x*d3.z;
    float a11 = d0.y*d0.y + d1.y*d1.y + d2.y*d2.y + d3.y*d3.y;
    float a12 = d0.y*d0.z + d1.y*d1.z + d2.y*d2.z + d3.y*d3.z;
    float a22 = d0.z*d0.z + d1.z*d1.z + d2.z*d2.z + d3.z*d3.z;
    V3 n = smallest_evec(a00, a01, a02, a11, a12, a22);
    float vd = -dot3(n, cm);
    float t;
    t = dot3(p0, n) + vd; st3(sp, i0, p0 - n*t);
    t = dot3(p1, n) + vd; st3(sp, i1, p1 - n*t);
    t = dot3(p2, n) + vd; st3(sp, i2, p2 - n*t);
    t = dot3(p3, n) + vd; st3(sp, i3, p3 - n*t);
}

// abduction for one finger (children {pip,dip,tip} rotated about mcp)
__device__ __forceinline__ void abduct(float* sp, int ia, int ib, float rectAng,
                                       int imcp, int ipip, int idip, int itip){
    V3 w  = ld3(sp, 0);
    V3 pa = ld3(sp, ia) - w, pb = ld3(sp, ib) - w;
    V3 mcp = ld3(sp, imcp), pip = ld3(sp, ipip);

    V3 palm = unitv(cross3(pa, pb));
    float vd   = -dot3(mcp, palm);
    float dist = dot3(pip, palm) + vd;
    V3 projpip = pip - palm*dist;
    float dis  = nrm3(mcp - pip);
    float flex = nrm3(projpip - mcp) / (dis + EPSF);
    flex = (flex < 0.3f) ? 0.0f : flex;
    V3 wristmcp = unitv(mcp - w);
    V3 mcpproj  = unitv(projpip - mcp);
    V3 mcppip   = unitv(pip - mcp);
    float cv = clampd(dot3(wristmcp, mcppip));
    bool overflex = cv < 0.00079632671073326f;   // == acos(cv) > 1.57
    float rs, rc;
    sincosf(rectAng, &rs, &rc);
    M3 Rr = rotmat(palm, rc, rs);
    V3 rect = mv(Rr, wristmcp);
    float ang = acosf(clampd(dot3(rect, mcpproj)));
    if (overflex) ang = 0.0f;
    M3 R = getrot(ang, flex, palm, mcpproj, wristmcp);

    st3(sp, ipip, mv(R, pip - mcp) + mcp);
    V3 c;
    c = ld3(sp, idip); st3(sp, idip, mv(R, c - mcp) + mcp);
    c = ld3(sp, itip); st3(sp, itip, mv(R, c - mcp) + mcp);
}

// plane rotation for one finger; rotates DIP & TIP about PIP
__device__ __forceinline__ void planerot(float* sp, int ia, int ib,
                                         int imcp, int ipip, int idip, int itip){
    V3 w  = ld3(sp, 0);
    V3 pa = ld3(sp, ia) - w, pb = ld3(sp, ib) - w;
    V3 mcp = ld3(sp, imcp), pip = ld3(sp, ipip), dip = ld3(sp, idip);

    V3 mcppip = unitv(pip - mcp);
    V3 pipdip = unitv(dip - pip);
    bool maskline = fabsf(dot3(mcppip, pipdip)) > 0.95f;
    V3 cdir = unitv(cross3(mcppip, pipdip));
    V3 palm = unitv(cross3(pa, pb));
    V3 stdv = unitv(cross3(unitv(mcp - w), palm));
    float ang = acosf(clampd(dot3(cdir, stdv)));
    if (maskline) ang = 0.0f;
    M3 R = getrot(ang, 1.0f, mcppip, cdir, stdv);

    st3(sp, idip, mv(R, dip - pip) + pip);
    V3 c = ld3(sp, itip);
    st3(sp, itip, mv(R, c - pip) + pip);
}

__global__ void __launch_bounds__(BLK, 6)
handpose_kernel(const float* __restrict__ in, float* __restrict__ out, int N){
    __shared__ float s[BLK * 63];
    int base = blockIdx.x * BLK;
    int nE = N - base; if (nE > BLK) nE = BLK;
    int nF = nE * 63;
    const float* gin = in + (long long)base * 63;

    if (nE == BLK) {
        // full block: vectorized staging (63*128 floats = 2016 float4, 16B-aligned)
        const float4* g4 = (const float4*)gin;
        float4* s4 = (float4*)s;
        #pragma unroll
        for (int k = 0; k < (BLK*63)/4/BLK; k++)
            s4[k*BLK + threadIdx.x] = g4[k*BLK + threadIdx.x];
        { int k = ((BLK*63)/4/BLK)*BLK + threadIdx.x;   // remainder (2016 = 15*128 + 96)
          if (k < (BLK*63)/4) s4[k] = g4[k]; }
    } else {
        for (int k = threadIdx.x; k < nF; k += BLK) s[k] = gin[k];
    }
    __syncthreads();

    if ((int)threadIdx.x < nE) {
        float* sp = s + threadIdx.x * 63;

        // ---- planarize #1 ----
        plan4(sp, 1,  2,  3,  17);
        plan4(sp, 4,  5,  6,  18);
        plan4(sp, 10, 11, 12, 19);
        plan4(sp, 7,  8,  9,  20);
        plan4(sp, 13, 14, 15, 16);

        // ---- abduction ----
        abduct(sp, 1,  4,   0.189f,  1,  2,  3,  17);
        abduct(sp, 4,  10,  0.1331f, 4,  5,  6,  18);
        abduct(sp, 10, 7,  -0.1491f, 10, 11, 12, 19);
        abduct(sp, 7,  1,   0.0347f, 7,  8,  9,  20);
        abduct(sp, 13, 1,   0.0f,    13, 14, 15, 16);

        // ---- plane rotation (fingers 0..3) ----
        planerot(sp, 1,  4,  1,  2,  3,  17);
        planerot(sp, 4,  10, 4,  5,  6,  18);
        planerot(sp, 10, 7,  10, 11, 12, 19);
        planerot(sp, 7,  1,  7,  8,  9,  20);

        // ---- planarize #2 ----
        plan4(sp, 1,  2,  3,  17);
        plan4(sp, 4,  5,  6,  18);
        plan4(sp, 10, 11, 12, 19);
        plan4(sp, 7,  8,  9,  20);
        plan4(sp, 13, 14, 15, 16);
    }
    __syncthreads();

    float* gout = out + (long long)base * 63;
    if (nE == BLK) {
        const float4* s4 = (const float4*)s;
        float4* g4 = (float4*)gout;
        #pragma unroll
        for (int k = 0; k < (BLK*63)/4/BLK; k++)
            g4[k*BLK + threadIdx.x] = s4[k*BLK + threadIdx.x];
        { int k = ((BLK*63)/4/BLK)*BLK + threadIdx.x;
          if (k < (BLK*63)/4) g4[k] = s4[k]; }
    } else {
        for (int k = threadIdx.x; k < nF; k += BLK) gout[k] = s[k];
    }
}

extern "C" void kernel_launch(void* const* d_in, const int* in_sizes, int n_in,
                              void* d_out, int out_size){
    const float* in = (const float*)d_in[0];
    float* out = (float*)d_out;
    int N = in_sizes[0] / 63;
    int grid = (N + BLK - 1) / BLK;
    handpose_kernel<<<grid, BLK>>>(in, out, N);
}